// round 15
// baseline (speedup 1.0000x reference)
#include <cuda_runtime.h>

#define NL 8192
#define NC 16384
#define BD 256
#define DD 64
#define SLOPE 0.01f
#define LCAP 64
#define CCAP 64
#define SCAPC 40

#define OUT_L 0
#define OUT_C 2097152
#define OUT_U 6291456

#define SCAN_BLOCKS 2048
#define PREP_BLOCKS (NL / 16)   // 512
#define COMB_BLOCKS 33
#define QB_BLOCKS   (NC / 16)   // 1024
#define PB_BLOCKS   (NL / 16)   // 512
#define OTHER_BLOCKS (PREP_BLOCKS + COMB_BLOCKS + QB_BLOCKS + PB_BLOCKS)  // 2081
#define MEGA_BLOCKS (SCAN_BLOCKS + OTHER_BLOCKS)                          // 4129

// ---------------- device scratch ----------------
__device__ float g_LT[(size_t)NL * BD];      // L_t node-major
__device__ float g_CnewT[(size_t)NC * BD];   // C_new node-major
__device__ float g_Q[(size_t)NC * BD];       // WCu1@C + bCu, node-major
__device__ float g_P[(size_t)NL * BD];       // WLu1@L + WLu3@Lflip + bLu, node-major
__device__ int   g_litCnt[NL];
__device__ int   g_litList[(size_t)NL * LCAP];
__device__ int   g_clauseCnt[NC];
__device__ int   g_clauseList[(size_t)NC * CCAP];
__device__ float g_Wcm[DD * DD];   // WCu2 @ WLmsg
__device__ float g_Wcl[DD * DD];   // WLu2 @ WCmsg
__device__ float g_bcm[DD];
__device__ float g_bcl[DD];
__device__ float g_sumL[BD];
__device__ float g_sumC[BD];

__device__ __forceinline__ float leaky(float x) { return x >= 0.f ? x : SLOPE * x; }

// acc2[8] (packed f32x2 pairs) += {w,w} * x[0..15]
#define FMA16P(acc2, wf, xptr) do {                                              \
    unsigned long long _w2;                                                      \
    asm("mov.b64 %0, {%1, %1};" : "=l"(_w2) : "f"(wf));                          \
    const ulonglong2* _x = (const ulonglong2*)(xptr);                            \
    ulonglong2 _p0 = _x[0]; ulonglong2 _p1 = _x[1];                              \
    ulonglong2 _p2 = _x[2]; ulonglong2 _p3 = _x[3];                              \
    asm("fma.rn.f32x2 %0, %1, %2, %0;" : "+l"(acc2[0]) : "l"(_w2), "l"(_p0.x));  \
    asm("fma.rn.f32x2 %0, %1, %2, %0;" : "+l"(acc2[1]) : "l"(_w2), "l"(_p0.y));  \
    asm("fma.rn.f32x2 %0, %1, %2, %0;" : "+l"(acc2[2]) : "l"(_w2), "l"(_p1.x));  \
    asm("fma.rn.f32x2 %0, %1, %2, %0;" : "+l"(acc2[3]) : "l"(_w2), "l"(_p1.y));  \
    asm("fma.rn.f32x2 %0, %1, %2, %0;" : "+l"(acc2[4]) : "l"(_w2), "l"(_p2.x));  \
    asm("fma.rn.f32x2 %0, %1, %2, %0;" : "+l"(acc2[5]) : "l"(_w2), "l"(_p2.y));  \
    asm("fma.rn.f32x2 %0, %1, %2, %0;" : "+l"(acc2[6]) : "l"(_w2), "l"(_p3.x));  \
    asm("fma.rn.f32x2 %0, %1, %2, %0;" : "+l"(acc2[7]) : "l"(_w2), "l"(_p3.y));  \
} while (0)

#define UNPACK16(acc, acc2)                                                       \
    _Pragma("unroll")                                                             \
    for (int _k = 0; _k < 8; _k++)                                                \
        asm("mov.b64 {%0, %1}, %2;" : "=f"(acc[2*_k]), "=f"(acc[2*_k+1]) : "l"(acc2[_k]));

// ---------------- kernels ----------------

// zeroing split into 3 tiny launches so k_mega is the 4th launch (profiled position)
__global__ void k_zeroA() {
    int i = blockIdx.x * blockDim.x + threadIdx.x;
    if (i < NL) g_litCnt[i] = 0;
}
__global__ void k_zeroB() {
    int i = blockIdx.x * blockDim.x + threadIdx.x;
    if (i < NC) g_clauseCnt[i] = 0;
}
__global__ void k_zeroC() {
    int i = threadIdx.x;
    g_sumL[i] = 0.f;
    g_sumC[i] = 0.f;
}

__device__ __forceinline__ void scan_add(int c, int l) {
    int p = atomicAdd(&g_clauseCnt[c], 1);
    if (p < CCAP) g_clauseList[(size_t)c * CCAP + p] = l;
    int q = atomicAdd(&g_litCnt[l], 1);
    if (q < LCAP) g_litList[(size_t)l * LCAP + q] = c;
}

__device__ __forceinline__ void scan_proc(uint4 v, unsigned idx) {
    if (v.x | v.y | v.z | v.w) {
        int c = idx >> 11;
        int lb = (idx & 2047) << 2;
        if (v.x) scan_add(c, lb);
        if (v.y) scan_add(c, lb + 1);
        if (v.z) scan_add(c, lb + 2);
        if (v.w) scan_add(c, lb + 3);
    }
}

// Heterogeneous mega-kernel, Bresenham-interleaved roles.
// Scan role is software-pipelined: batch t+1's loads issue BEFORE batch t's
// processing, so atomic latency hides under the next DRAM wait.
__global__ __launch_bounds__(256) void k_mega(const uint4* __restrict__ A4,
                                              const float* __restrict__ L,
                                              const float* __restrict__ C,
                                              const float* __restrict__ WCu,
                                              const float* __restrict__ WLmsg,
                                              const float* __restrict__ bLmsg,
                                              const float* __restrict__ WLu,
                                              const float* __restrict__ WCmsg,
                                              const float* __restrict__ bCmsg,
                                              const float* __restrict__ bCu,
                                              const float* __restrict__ bLu) {
    __shared__ float smem_buf[256 * 20 + 64];   // 20.75KB union buffer
    int bid = blockIdx.x;
    int tid = threadIdx.x;

    int s_lo = (int)(((long long)bid * SCAN_BLOCKS) / MEGA_BLOCKS);
    int s_hi = (int)(((long long)(bid + 1) * SCAN_BLOCKS) / MEGA_BLOCKS);
    bool is_scan = (s_hi > s_lo);
    int scan_id = s_lo;
    int other_id = bid - s_lo;

    if (is_scan) {
        const unsigned stride = SCAN_BLOCKS * 256u;
        unsigned i = scan_id * 256u + tid;
        // prologue: load batch 0
        uint4 c0 = __ldcs(&A4[i]);
        uint4 c1 = __ldcs(&A4[i + stride]);
        uint4 c2 = __ldcs(&A4[i + 2 * stride]);
        uint4 c3 = __ldcs(&A4[i + 3 * stride]);
        uint4 c4 = __ldcs(&A4[i + 4 * stride]);
        uint4 c5 = __ldcs(&A4[i + 5 * stride]);
        uint4 c6 = __ldcs(&A4[i + 6 * stride]);
        uint4 c7 = __ldcs(&A4[i + 7 * stride]);
        #pragma unroll 1
        for (int t = 0; t < 7; t++) {
            unsigned nb = i + 8u * stride;
            // prefetch batch t+1
            uint4 n0 = __ldcs(&A4[nb]);
            uint4 n1 = __ldcs(&A4[nb + stride]);
            uint4 n2 = __ldcs(&A4[nb + 2 * stride]);
            uint4 n3 = __ldcs(&A4[nb + 3 * stride]);
            uint4 n4 = __ldcs(&A4[nb + 4 * stride]);
            uint4 n5 = __ldcs(&A4[nb + 5 * stride]);
            uint4 n6 = __ldcs(&A4[nb + 6 * stride]);
            uint4 n7 = __ldcs(&A4[nb + 7 * stride]);
            // process batch t (atomics overlap batch t+1's load latency)
            unsigned any = (c0.x | c0.y | c0.z | c0.w) | (c1.x | c1.y | c1.z | c1.w)
                         | (c2.x | c2.y | c2.z | c2.w) | (c3.x | c3.y | c3.z | c3.w)
                         | (c4.x | c4.y | c4.z | c4.w) | (c5.x | c5.y | c5.z | c5.w)
                         | (c6.x | c6.y | c6.z | c6.w) | (c7.x | c7.y | c7.z | c7.w);
            if (any) {
                scan_proc(c0, i);
                scan_proc(c1, i + stride);
                scan_proc(c2, i + 2 * stride);
                scan_proc(c3, i + 3 * stride);
                scan_proc(c4, i + 4 * stride);
                scan_proc(c5, i + 5 * stride);
                scan_proc(c6, i + 6 * stride);
                scan_proc(c7, i + 7 * stride);
            }
            c0 = n0; c1 = n1; c2 = n2; c3 = n3;
            c4 = n4; c5 = n5; c6 = n6; c7 = n7;
            i = nb;
        }
        // epilogue: process final batch
        {
            unsigned any = (c0.x | c0.y | c0.z | c0.w) | (c1.x | c1.y | c1.z | c1.w)
                         | (c2.x | c2.y | c2.z | c2.w) | (c3.x | c3.y | c3.z | c3.w)
                         | (c4.x | c4.y | c4.z | c4.w) | (c5.x | c5.y | c5.z | c5.w)
                         | (c6.x | c6.y | c6.z | c6.w) | (c7.x | c7.y | c7.z | c7.w);
            if (any) {
                scan_proc(c0, i);
                scan_proc(c1, i + stride);
                scan_proc(c2, i + 2 * stride);
                scan_proc(c3, i + 3 * stride);
                scan_proc(c4, i + 4 * stride);
                scan_proc(c5, i + 5 * stride);
                scan_proc(c6, i + 6 * stride);
                scan_proc(c7, i + 7 * stride);
            }
        }
    } else if (other_id < PREP_BLOCKS) {
        // transpose L_t [256][NL] -> g_LT [NL][256], 16 literals
        float* s = smem_buf;   // 256*17
        int l0 = other_id * 16;
        for (int idx = tid; idx < 256 * 16; idx += 256) {
            int r = idx >> 4, c = idx & 15;
            s[r * 17 + c] = L[(size_t)r * NL + l0 + c];
        }
        __syncthreads();
        #pragma unroll
        for (int li = 0; li < 16; li++)
            g_LT[(size_t)(l0 + li) * BD + tid] = s[tid * 17 + li];
    } else if (other_id < PREP_BLOCKS + COMB_BLOCKS) {
        int idx = (other_id - PREP_BLOCKS) * 256 + tid;
        if (idx < 4096) {
            int o = idx >> 6, i = idx & 63;
            float s = 0.f;
            #pragma unroll
            for (int j = 0; j < 64; j++) s += WCu[o * 128 + 64 + j] * WLmsg[j * 64 + i];
            g_Wcm[idx] = s;
        } else if (idx < 8192) {
            int k = idx - 4096;
            int o = k >> 6, i = k & 63;
            float s = 0.f;
            #pragma unroll
            for (int j = 0; j < 64; j++) s += WLu[o * 192 + 64 + j] * WCmsg[j * 64 + i];
            g_Wcl[k] = s;
        } else if (idx < 8256) {
            int o = idx - 8192;
            float s = 0.f;
            #pragma unroll
            for (int j = 0; j < 64; j++) s += WCu[o * 128 + 64 + j] * bLmsg[j];
            g_bcm[o] = s;
        } else if (idx < 8320) {
            int o = idx - 8256;
            float s = 0.f;
            #pragma unroll
            for (int j = 0; j < 64; j++) s += WLu[o * 192 + 64 + j] * bCmsg[j];
            g_bcl[o] = s;
        }
    } else if (other_id < PREP_BLOCKS + COMB_BLOCKS + QB_BLOCKS) {
        // Q tile: WCu1 @ C + bCu, 16 clauses
        float* s_ct = smem_buf;   // 256*20
        int c0 = (other_id - PREP_BLOCKS - COMB_BLOCKS) * 16;
        for (int idx = tid; idx < 256 * 16; idx += 256) {
            int r = idx >> 4, cc = idx & 15;
            s_ct[r * 20 + cc] = C[(size_t)r * NC + c0 + cc];
        }
        __syncthreads();
        int b = tid >> 6, ch = tid & 63;
        unsigned long long acc2[8];
        #pragma unroll
        for (int i = 0; i < 8; i++) acc2[i] = 0ull;
        const float4* w = (const float4*)(WCu + ch * 128);
        #pragma unroll 4
        for (int j4 = 0; j4 < 16; j4++) {
            float4 wv = __ldg(&w[j4]);
            const float* x = s_ct + (b * 64 + j4 * 4) * 20;
            FMA16P(acc2, wv.x, x);
            FMA16P(acc2, wv.y, x + 20);
            FMA16P(acc2, wv.z, x + 40);
            FMA16P(acc2, wv.w, x + 60);
        }
        float acc[16];
        UNPACK16(acc, acc2);
        float bb = __ldg(&bCu[ch]);
        #pragma unroll
        for (int cc = 0; cc < 16; cc++)
            g_Q[(size_t)(c0 + cc) * BD + tid] = acc[cc] + bb;
    } else {
        // P tile: WLu1 @ L + WLu3 @ L_flip + bLu — two-pass over one buffer
        float* s_X = smem_buf;   // 256*20
        int l0 = (other_id - PREP_BLOCKS - COMB_BLOCKS - QB_BLOCKS) * 16;
        int lf0 = (l0 + 4096) & (NL - 1);
        for (int idx = tid; idx < 256 * 16; idx += 256) {
            int r = idx >> 4, cc = idx & 15;
            s_X[r * 20 + cc] = L[(size_t)r * NL + l0 + cc];
        }
        __syncthreads();
        int b = tid >> 6, ch = tid & 63;
        unsigned long long acc2[8];
        #pragma unroll
        for (int i = 0; i < 8; i++) acc2[i] = 0ull;
        const float4* w1 = (const float4*)(WLu + ch * 192);
        const float4* w3 = (const float4*)(WLu + ch * 192 + 128);
        #pragma unroll 4
        for (int j4 = 0; j4 < 16; j4++) {
            float4 wv = __ldg(&w1[j4]);
            const float* x = s_X + (b * 64 + j4 * 4) * 20;
            FMA16P(acc2, wv.x, x);
            FMA16P(acc2, wv.y, x + 20);
            FMA16P(acc2, wv.z, x + 40);
            FMA16P(acc2, wv.w, x + 60);
        }
        __syncthreads();
        for (int idx = tid; idx < 256 * 16; idx += 256) {
            int r = idx >> 4, cc = idx & 15;
            s_X[r * 20 + cc] = L[(size_t)r * NL + lf0 + cc];
        }
        __syncthreads();
        #pragma unroll 4
        for (int j4 = 0; j4 < 16; j4++) {
            float4 wv = __ldg(&w3[j4]);
            const float* x = s_X + (b * 64 + j4 * 4) * 20;
            FMA16P(acc2, wv.x, x);
            FMA16P(acc2, wv.y, x + 20);
            FMA16P(acc2, wv.z, x + 40);
            FMA16P(acc2, wv.w, x + 60);
        }
        float acc[16];
        UNPACK16(acc, acc2);
        float bb = __ldg(&bLu[ch]);
        #pragma unroll
        for (int cc = 0; cc < 16; cc++)
            g_P[(size_t)(l0 + cc) * BD + tid] = acc[cc] + bb;
    }
}

// Clause update: gather g_LT + Wcm matvec + Q.
__global__ __launch_bounds__(256) void k_clauseUp(float* __restrict__ outC) {
    extern __shared__ float sm[];
    float* s_S   = sm;                     // 256*20
    int*   s_cnt = (int*)(s_S + 256 * 20); // 16
    int*   s_list = s_cnt + 16;            // 16*SCAPC

    int tid = threadIdx.x;
    int c0 = blockIdx.x * 16;

    if (tid < 16) s_cnt[tid] = min(g_clauseCnt[c0 + tid], SCAPC);
    __syncthreads();
    for (int idx = tid; idx < 16 * SCAPC; idx += 256) {
        int cc = idx / SCAPC, i = idx - cc * SCAPC;
        if (i < s_cnt[cc]) s_list[idx] = g_clauseList[(size_t)(c0 + cc) * CCAP + i];
    }
    __syncthreads();

    #pragma unroll 1
    for (int cc = 0; cc < 16; cc++) {
        int cnt = s_cnt[cc];
        const int* lst = s_list + cc * SCAPC;
        float m0 = 0.f, m1 = 0.f, m2 = 0.f, m3 = 0.f;
        float m4 = 0.f, m5 = 0.f, m6 = 0.f, m7 = 0.f;
        int i = 0;
        for (; i + 7 < cnt; i += 8) {
            m0 += __ldg(&g_LT[(size_t)lst[i]     * BD + tid]);
            m1 += __ldg(&g_LT[(size_t)lst[i + 1] * BD + tid]);
            m2 += __ldg(&g_LT[(size_t)lst[i + 2] * BD + tid]);
            m3 += __ldg(&g_LT[(size_t)lst[i + 3] * BD + tid]);
            m4 += __ldg(&g_LT[(size_t)lst[i + 4] * BD + tid]);
            m5 += __ldg(&g_LT[(size_t)lst[i + 5] * BD + tid]);
            m6 += __ldg(&g_LT[(size_t)lst[i + 6] * BD + tid]);
            m7 += __ldg(&g_LT[(size_t)lst[i + 7] * BD + tid]);
        }
        for (; i < cnt; i++) m0 += __ldg(&g_LT[(size_t)lst[i] * BD + tid]);
        s_S[tid * 20 + cc] = ((m0 + m1) + (m2 + m3)) + ((m4 + m5) + (m6 + m7));
    }
    __syncthreads();

    int b = tid >> 6, ch = tid & 63;
    unsigned long long acc2[8];
    #pragma unroll
    for (int i = 0; i < 8; i++) acc2[i] = 0ull;
    const float4* wc = (const float4*)(g_Wcm + ch * 64);
    #pragma unroll 4
    for (int j4 = 0; j4 < 16; j4++) {
        float4 wv = __ldg(&wc[j4]);
        const float* x = s_S + (b * 64 + j4 * 4) * 20;
        FMA16P(acc2, wv.x, x);
        FMA16P(acc2, wv.y, x + 20);
        FMA16P(acc2, wv.z, x + 40);
        FMA16P(acc2, wv.w, x + 60);
    }
    float acc[16];
    UNPACK16(acc, acc2);

    float bc = __ldg(&g_bcm[ch]);
    float lsum = 0.f;
    #pragma unroll
    for (int cc = 0; cc < 16; cc++) {
        float q = __ldg(&g_Q[(size_t)(c0 + cc) * BD + tid]);
        float v = leaky(acc[cc] + q + (float)s_cnt[cc] * bc);
        acc[cc] = v;
        lsum += v;
        g_CnewT[(size_t)(c0 + cc) * BD + tid] = v;
    }
    float4* orow = (float4*)(outC + (size_t)tid * NC + c0);
    orow[0] = make_float4(acc[0], acc[1], acc[2], acc[3]);
    orow[1] = make_float4(acc[4], acc[5], acc[6], acc[7]);
    orow[2] = make_float4(acc[8], acc[9], acc[10], acc[11]);
    orow[3] = make_float4(acc[12], acc[13], acc[14], acc[15]);
    atomicAdd(&g_sumC[tid], lsum);
}

// Literal update: gather C_new + Wcl matvec + P.
__global__ __launch_bounds__(256) void k_literalUp(float* __restrict__ outL) {
    extern __shared__ float sm[];
    float* s_S   = sm;                     // 256*20
    int*   s_cnt = (int*)(s_S + 256 * 20); // 16
    int*   s_list = s_cnt + 16;            // 16*LCAP

    int tid = threadIdx.x;
    int l0 = blockIdx.x * 16;

    if (tid < 16) s_cnt[tid] = min(g_litCnt[l0 + tid], LCAP);
    __syncthreads();
    for (int idx = tid; idx < 16 * LCAP; idx += 256) {
        int cc = idx >> 6, i = idx & 63;
        if (i < s_cnt[cc]) s_list[idx] = g_litList[(size_t)(l0 + cc) * LCAP + i];
    }
    __syncthreads();

    #pragma unroll 1
    for (int cc = 0; cc < 16; cc++) {
        int cnt = s_cnt[cc];
        const int* lst = s_list + cc * LCAP;
        float m0 = 0.f, m1 = 0.f, m2 = 0.f, m3 = 0.f;
        float m4 = 0.f, m5 = 0.f, m6 = 0.f, m7 = 0.f;
        int i = 0;
        for (; i + 7 < cnt; i += 8) {
            m0 += __ldg(&g_CnewT[(size_t)lst[i]     * BD + tid]);
            m1 += __ldg(&g_CnewT[(size_t)lst[i + 1] * BD + tid]);
            m2 += __ldg(&g_CnewT[(size_t)lst[i + 2] * BD + tid]);
            m3 += __ldg(&g_CnewT[(size_t)lst[i + 3] * BD + tid]);
            m4 += __ldg(&g_CnewT[(size_t)lst[i + 4] * BD + tid]);
            m5 += __ldg(&g_CnewT[(size_t)lst[i + 5] * BD + tid]);
            m6 += __ldg(&g_CnewT[(size_t)lst[i + 6] * BD + tid]);
            m7 += __ldg(&g_CnewT[(size_t)lst[i + 7] * BD + tid]);
        }
        for (; i < cnt; i++) m0 += __ldg(&g_CnewT[(size_t)lst[i] * BD + tid]);
        s_S[tid * 20 + cc] = ((m0 + m1) + (m2 + m3)) + ((m4 + m5) + (m6 + m7));
    }
    __syncthreads();

    int b = tid >> 6, ch = tid & 63;
    unsigned long long acc2[8];
    #pragma unroll
    for (int i = 0; i < 8; i++) acc2[i] = 0ull;
    const float4* wl = (const float4*)(g_Wcl + ch * 64);
    #pragma unroll 4
    for (int j4 = 0; j4 < 16; j4++) {
        float4 wv = __ldg(&wl[j4]);
        const float* x = s_S + (b * 64 + j4 * 4) * 20;
        FMA16P(acc2, wv.x, x);
        FMA16P(acc2, wv.y, x + 20);
        FMA16P(acc2, wv.z, x + 40);
        FMA16P(acc2, wv.w, x + 60);
    }
    float acc[16];
    UNPACK16(acc, acc2);

    float bc = __ldg(&g_bcl[ch]);
    float lsum = 0.f;
    #pragma unroll
    for (int cc = 0; cc < 16; cc++) {
        float p = __ldg(&g_P[(size_t)(l0 + cc) * BD + tid]);
        float v = leaky(acc[cc] + p + (float)s_cnt[cc] * bc);
        acc[cc] = v;
        lsum += v;
    }
    float4* orow = (float4*)(outL + (size_t)tid * NL + l0);
    orow[0] = make_float4(acc[0], acc[1], acc[2], acc[3]);
    orow[1] = make_float4(acc[4], acc[5], acc[6], acc[7]);
    orow[2] = make_float4(acc[8], acc[9], acc[10], acc[11]);
    orow[3] = make_float4(acc[12], acc[13], acc[14], acc[15]);
    atomicAdd(&g_sumL[tid], lsum);
}

__global__ void k_U(const float* __restrict__ U, const float* __restrict__ WUu,
                    const float* __restrict__ bUu, float* __restrict__ out) {
    __shared__ float glb[4 * 192];
    int tid = threadIdx.x;
    int b = tid >> 6, ch = tid & 63;
    glb[b * 192 + ch]       = g_sumL[tid];
    glb[b * 192 + 64 + ch]  = g_sumC[tid];
    glb[b * 192 + 128 + ch] = U[tid];
    __syncthreads();
    float s = bUu[ch];
    #pragma unroll 8
    for (int i = 0; i < 192; i++) s += WUu[ch * 192 + i] * glb[b * 192 + i];
    out[tid] = leaky(s);
}

// ---------------- launch ----------------
extern "C" void kernel_launch(void* const* d_in, const int* in_sizes, int n_in,
                              void* d_out, int out_size) {
    const float* L     = (const float*)d_in[0];
    const float* C     = (const float*)d_in[1];
    const float* U     = (const float*)d_in[2];
    const float* A     = (const float*)d_in[3];
    const float* WLmsg = (const float*)d_in[5];
    const float* bLmsg = (const float*)d_in[6];
    const float* WCmsg = (const float*)d_in[7];
    const float* bCmsg = (const float*)d_in[8];
    const float* WLu   = (const float*)d_in[9];
    const float* bLu   = (const float*)d_in[10];
    const float* WCu   = (const float*)d_in[11];
    const float* bCu   = (const float*)d_in[12];
    const float* WUu   = (const float*)d_in[13];
    const float* bUu   = (const float*)d_in[14];
    float* out = (float*)d_out;

    const int smem_clause  = (256 * 20 + 16 + 16 * SCAPC) * 4;
    const int smem_literal = (256 * 20 + 16 + 16 * LCAP) * 4;
    cudaFuncSetAttribute(k_clauseUp,  cudaFuncAttributeMaxDynamicSharedMemorySize, smem_clause);
    cudaFuncSetAttribute(k_literalUp, cudaFuncAttributeMaxDynamicSharedMemorySize, smem_literal);

    k_zeroA<<<32, 256>>>();
    k_zeroB<<<64, 256>>>();
    k_zeroC<<<1, 256>>>();
    k_mega<<<MEGA_BLOCKS, 256>>>((const uint4*)A, L, C, WCu, WLmsg, bLmsg,
                                 WLu, WCmsg, bCmsg, bCu, bLu);
    k_clauseUp<<<NC / 16, 256, smem_clause>>>(out + OUT_C);
    k_literalUp<<<NL / 16, 256, smem_literal>>>(out + OUT_L);
    k_U<<<1, 256>>>(U, WUu, bUu, out + OUT_U);
}

// round 16
// speedup vs baseline: 1.1401x; 1.1401x over previous
#include <cuda_runtime.h>

#define NL 8192
#define NC 16384
#define BD 256
#define DD 64
#define SLOPE 0.01f
#define LCAP 64
#define CCAP 64
#define SCAPC 40

#define OUT_L 0
#define OUT_C 2097152
#define OUT_U 6291456

#define SCAN_BLOCKS 2048
#define PREP_BLOCKS (NL / 16)   // 512
#define COMB_BLOCKS 33
#define QB_BLOCKS   (NC / 16)   // 1024
#define PB_BLOCKS   (NL / 16)   // 512
#define OTHER_BLOCKS (PREP_BLOCKS + COMB_BLOCKS + QB_BLOCKS + PB_BLOCKS)  // 2081
#define MEGA_BLOCKS (SCAN_BLOCKS + OTHER_BLOCKS)                          // 4129

// ---------------- device scratch ----------------
__device__ float g_LT[(size_t)NL * BD];      // L_t node-major
__device__ float g_CnewT[(size_t)NC * BD];   // C_new node-major
__device__ float g_Q[(size_t)NC * BD];       // WCu1@C + bCu, node-major
__device__ float g_P[(size_t)NL * BD];       // WLu1@L + WLu3@Lflip + bLu, node-major
__device__ int   g_litCnt[NL];
__device__ int   g_litList[(size_t)NL * LCAP];
__device__ int   g_clauseCnt[NC];
__device__ int   g_clauseList[(size_t)NC * CCAP];
__device__ float g_Wcm[DD * DD];   // WCu2 @ WLmsg
__device__ float g_Wcl[DD * DD];   // WLu2 @ WCmsg
__device__ float g_bcm[DD];
__device__ float g_bcl[DD];
__device__ float g_sumL[BD];
__device__ float g_sumC[BD];

__device__ __forceinline__ float leaky(float x) { return x >= 0.f ? x : SLOPE * x; }

// acc2[8] (packed f32x2 pairs) += {w,w} * x[0..15]
#define FMA16P(acc2, wf, xptr) do {                                              \
    unsigned long long _w2;                                                      \
    asm("mov.b64 %0, {%1, %1};" : "=l"(_w2) : "f"(wf));                          \
    const ulonglong2* _x = (const ulonglong2*)(xptr);                            \
    ulonglong2 _p0 = _x[0]; ulonglong2 _p1 = _x[1];                              \
    ulonglong2 _p2 = _x[2]; ulonglong2 _p3 = _x[3];                              \
    asm("fma.rn.f32x2 %0, %1, %2, %0;" : "+l"(acc2[0]) : "l"(_w2), "l"(_p0.x));  \
    asm("fma.rn.f32x2 %0, %1, %2, %0;" : "+l"(acc2[1]) : "l"(_w2), "l"(_p0.y));  \
    asm("fma.rn.f32x2 %0, %1, %2, %0;" : "+l"(acc2[2]) : "l"(_w2), "l"(_p1.x));  \
    asm("fma.rn.f32x2 %0, %1, %2, %0;" : "+l"(acc2[3]) : "l"(_w2), "l"(_p1.y));  \
    asm("fma.rn.f32x2 %0, %1, %2, %0;" : "+l"(acc2[4]) : "l"(_w2), "l"(_p2.x));  \
    asm("fma.rn.f32x2 %0, %1, %2, %0;" : "+l"(acc2[5]) : "l"(_w2), "l"(_p2.y));  \
    asm("fma.rn.f32x2 %0, %1, %2, %0;" : "+l"(acc2[6]) : "l"(_w2), "l"(_p3.x));  \
    asm("fma.rn.f32x2 %0, %1, %2, %0;" : "+l"(acc2[7]) : "l"(_w2), "l"(_p3.y));  \
} while (0)

#define UNPACK16(acc, acc2)                                                       \
    _Pragma("unroll")                                                             \
    for (int _k = 0; _k < 8; _k++)                                                \
        asm("mov.b64 {%0, %1}, %2;" : "=f"(acc[2*_k]), "=f"(acc[2*_k+1]) : "l"(acc2[_k]));

// ---------------- kernels ----------------

__global__ void k_zeroA() {
    int i = blockIdx.x * blockDim.x + threadIdx.x;
    if (i < NL) g_litCnt[i] = 0;
}
__global__ void k_zeroB() {
    int i = blockIdx.x * blockDim.x + threadIdx.x;
    if (i < NC) g_clauseCnt[i] = 0;
}
__global__ void k_zeroC() {
    int i = threadIdx.x;
    g_sumL[i] = 0.f;
    g_sumC[i] = 0.f;
}

__device__ __forceinline__ void scan_add(int c, int l) {
    int p = atomicAdd(&g_clauseCnt[c], 1);
    if (p < CCAP) g_clauseList[(size_t)c * CCAP + p] = l;
    int q = atomicAdd(&g_litCnt[l], 1);
    if (q < LCAP) g_litList[(size_t)l * LCAP + q] = c;
}

__device__ __forceinline__ void scan_proc(uint4 v, unsigned idx) {
    if (v.x | v.y | v.z | v.w) {
        int c = idx >> 11;
        int lb = (idx & 2047) << 2;
        if (v.x) scan_add(c, lb);
        if (v.y) scan_add(c, lb + 1);
        if (v.z) scan_add(c, lb + 2);
        if (v.w) scan_add(c, lb + 3);
    }
}

// Heterogeneous mega-kernel, Bresenham-interleaved roles.
// Scan role uses a 4-stage cp.async smem ring: bytes-in-flight live in smem,
// not registers, so DRAM stays saturated at modest occupancy.
__global__ __launch_bounds__(256, 4) void k_mega(const uint4* __restrict__ A4,
                                                 const float* __restrict__ L,
                                                 const float* __restrict__ C,
                                                 const float* __restrict__ WCu,
                                                 const float* __restrict__ WLmsg,
                                                 const float* __restrict__ bLmsg,
                                                 const float* __restrict__ WLu,
                                                 const float* __restrict__ WCmsg,
                                                 const float* __restrict__ bCmsg,
                                                 const float* __restrict__ bCu,
                                                 const float* __restrict__ bLu) {
    __shared__ float smem_buf[256 * 20 + 64];   // 20.75KB union buffer
    int bid = blockIdx.x;
    int tid = threadIdx.x;

    int s_lo = (int)(((long long)bid * SCAN_BLOCKS) / MEGA_BLOCKS);
    int s_hi = (int)(((long long)(bid + 1) * SCAN_BLOCKS) / MEGA_BLOCKS);
    bool is_scan = (s_hi > s_lo);
    int scan_id = s_lo;
    int other_id = bid - s_lo;

    if (is_scan) {
        // 4-stage cp.async ring: stage s holds 256 x 16B; thread owns one slot.
        const unsigned stride = SCAN_BLOCKS * 256u;
        unsigned base = scan_id * 256u + tid;
        uint4* sring = (uint4*)smem_buf;                   // 4 * 256 entries = 16KB
        unsigned my_slot_addr;
        {
            uint4* p = &sring[tid];
            my_slot_addr = (unsigned)__cvta_generic_to_shared(p);
        }
        // prologue: stages 0..2
        #pragma unroll
        for (int s = 0; s < 3; s++) {
            unsigned dst = my_slot_addr + (unsigned)s * 256u * 16u;
            const uint4* src = &A4[base + (unsigned)s * stride];
            asm volatile("cp.async.cg.shared.global [%0], [%1], 16;"
                         :: "r"(dst), "l"(src) : "memory");
            asm volatile("cp.async.commit_group;" ::: "memory");
        }
        #pragma unroll 1
        for (int t = 0; t < 64; t++) {
            if (t + 3 < 64) {
                unsigned dst = my_slot_addr + (unsigned)((t + 3) & 3) * 256u * 16u;
                const uint4* src = &A4[base + (unsigned)(t + 3) * stride];
                asm volatile("cp.async.cg.shared.global [%0], [%1], 16;"
                             :: "r"(dst), "l"(src) : "memory");
            }
            asm volatile("cp.async.commit_group;" ::: "memory");
            asm volatile("cp.async.wait_group 3;" ::: "memory");
            uint4 v = sring[((t & 3) << 8) + tid];
            scan_proc(v, base + (unsigned)t * stride);
        }
    } else if (other_id < PREP_BLOCKS) {
        // transpose L_t [256][NL] -> g_LT [NL][256], 16 literals
        float* s = smem_buf;   // 256*17
        int l0 = other_id * 16;
        for (int idx = tid; idx < 256 * 16; idx += 256) {
            int r = idx >> 4, c = idx & 15;
            s[r * 17 + c] = L[(size_t)r * NL + l0 + c];
        }
        __syncthreads();
        #pragma unroll
        for (int li = 0; li < 16; li++)
            g_LT[(size_t)(l0 + li) * BD + tid] = s[tid * 17 + li];
    } else if (other_id < PREP_BLOCKS + COMB_BLOCKS) {
        int idx = (other_id - PREP_BLOCKS) * 256 + tid;
        if (idx < 4096) {
            int o = idx >> 6, i = idx & 63;
            float s = 0.f;
            #pragma unroll
            for (int j = 0; j < 64; j++) s += WCu[o * 128 + 64 + j] * WLmsg[j * 64 + i];
            g_Wcm[idx] = s;
        } else if (idx < 8192) {
            int k = idx - 4096;
            int o = k >> 6, i = k & 63;
            float s = 0.f;
            #pragma unroll
            for (int j = 0; j < 64; j++) s += WLu[o * 192 + 64 + j] * WCmsg[j * 64 + i];
            g_Wcl[k] = s;
        } else if (idx < 8256) {
            int o = idx - 8192;
            float s = 0.f;
            #pragma unroll
            for (int j = 0; j < 64; j++) s += WCu[o * 128 + 64 + j] * bLmsg[j];
            g_bcm[o] = s;
        } else if (idx < 8320) {
            int o = idx - 8256;
            float s = 0.f;
            #pragma unroll
            for (int j = 0; j < 64; j++) s += WLu[o * 192 + 64 + j] * bCmsg[j];
            g_bcl[o] = s;
        }
    } else if (other_id < PREP_BLOCKS + COMB_BLOCKS + QB_BLOCKS) {
        // Q tile: WCu1 @ C + bCu, 16 clauses
        float* s_ct = smem_buf;   // 256*20
        int c0 = (other_id - PREP_BLOCKS - COMB_BLOCKS) * 16;
        for (int idx = tid; idx < 256 * 16; idx += 256) {
            int r = idx >> 4, cc = idx & 15;
            s_ct[r * 20 + cc] = C[(size_t)r * NC + c0 + cc];
        }
        __syncthreads();
        int b = tid >> 6, ch = tid & 63;
        unsigned long long acc2[8];
        #pragma unroll
        for (int i = 0; i < 8; i++) acc2[i] = 0ull;
        const float4* w = (const float4*)(WCu + ch * 128);
        #pragma unroll 4
        for (int j4 = 0; j4 < 16; j4++) {
            float4 wv = __ldg(&w[j4]);
            const float* x = s_ct + (b * 64 + j4 * 4) * 20;
            FMA16P(acc2, wv.x, x);
            FMA16P(acc2, wv.y, x + 20);
            FMA16P(acc2, wv.z, x + 40);
            FMA16P(acc2, wv.w, x + 60);
        }
        float acc[16];
        UNPACK16(acc, acc2);
        float bb = __ldg(&bCu[ch]);
        #pragma unroll
        for (int cc = 0; cc < 16; cc++)
            g_Q[(size_t)(c0 + cc) * BD + tid] = acc[cc] + bb;
    } else {
        // P tile: WLu1 @ L + WLu3 @ L_flip + bLu — two-pass over one buffer
        float* s_X = smem_buf;   // 256*20
        int l0 = (other_id - PREP_BLOCKS - COMB_BLOCKS - QB_BLOCKS) * 16;
        int lf0 = (l0 + 4096) & (NL - 1);
        for (int idx = tid; idx < 256 * 16; idx += 256) {
            int r = idx >> 4, cc = idx & 15;
            s_X[r * 20 + cc] = L[(size_t)r * NL + l0 + cc];
        }
        __syncthreads();
        int b = tid >> 6, ch = tid & 63;
        unsigned long long acc2[8];
        #pragma unroll
        for (int i = 0; i < 8; i++) acc2[i] = 0ull;
        const float4* w1 = (const float4*)(WLu + ch * 192);
        const float4* w3 = (const float4*)(WLu + ch * 192 + 128);
        #pragma unroll 4
        for (int j4 = 0; j4 < 16; j4++) {
            float4 wv = __ldg(&w1[j4]);
            const float* x = s_X + (b * 64 + j4 * 4) * 20;
            FMA16P(acc2, wv.x, x);
            FMA16P(acc2, wv.y, x + 20);
            FMA16P(acc2, wv.z, x + 40);
            FMA16P(acc2, wv.w, x + 60);
        }
        __syncthreads();
        for (int idx = tid; idx < 256 * 16; idx += 256) {
            int r = idx >> 4, cc = idx & 15;
            s_X[r * 20 + cc] = L[(size_t)r * NL + lf0 + cc];
        }
        __syncthreads();
        #pragma unroll 4
        for (int j4 = 0; j4 < 16; j4++) {
            float4 wv = __ldg(&w3[j4]);
            const float* x = s_X + (b * 64 + j4 * 4) * 20;
            FMA16P(acc2, wv.x, x);
            FMA16P(acc2, wv.y, x + 20);
            FMA16P(acc2, wv.z, x + 40);
            FMA16P(acc2, wv.w, x + 60);
        }
        float acc[16];
        UNPACK16(acc, acc2);
        float bb = __ldg(&bLu[ch]);
        #pragma unroll
        for (int cc = 0; cc < 16; cc++)
            g_P[(size_t)(l0 + cc) * BD + tid] = acc[cc] + bb;
    }
}

// Clause update: gather g_LT + Wcm matvec + Q.
__global__ __launch_bounds__(256) void k_clauseUp(float* __restrict__ outC) {
    extern __shared__ float sm[];
    float* s_S   = sm;                     // 256*20
    int*   s_cnt = (int*)(s_S + 256 * 20); // 16
    int*   s_list = s_cnt + 16;            // 16*SCAPC

    int tid = threadIdx.x;
    int c0 = blockIdx.x * 16;

    if (tid < 16) s_cnt[tid] = min(g_clauseCnt[c0 + tid], SCAPC);
    __syncthreads();
    for (int idx = tid; idx < 16 * SCAPC; idx += 256) {
        int cc = idx / SCAPC, i = idx - cc * SCAPC;
        if (i < s_cnt[cc]) s_list[idx] = g_clauseList[(size_t)(c0 + cc) * CCAP + i];
    }
    __syncthreads();

    #pragma unroll 1
    for (int cc = 0; cc < 16; cc++) {
        int cnt = s_cnt[cc];
        const int* lst = s_list + cc * SCAPC;
        float m0 = 0.f, m1 = 0.f, m2 = 0.f, m3 = 0.f;
        float m4 = 0.f, m5 = 0.f, m6 = 0.f, m7 = 0.f;
        int i = 0;
        for (; i + 7 < cnt; i += 8) {
            m0 += __ldg(&g_LT[(size_t)lst[i]     * BD + tid]);
            m1 += __ldg(&g_LT[(size_t)lst[i + 1] * BD + tid]);
            m2 += __ldg(&g_LT[(size_t)lst[i + 2] * BD + tid]);
            m3 += __ldg(&g_LT[(size_t)lst[i + 3] * BD + tid]);
            m4 += __ldg(&g_LT[(size_t)lst[i + 4] * BD + tid]);
            m5 += __ldg(&g_LT[(size_t)lst[i + 5] * BD + tid]);
            m6 += __ldg(&g_LT[(size_t)lst[i + 6] * BD + tid]);
            m7 += __ldg(&g_LT[(size_t)lst[i + 7] * BD + tid]);
        }
        for (; i < cnt; i++) m0 += __ldg(&g_LT[(size_t)lst[i] * BD + tid]);
        s_S[tid * 20 + cc] = ((m0 + m1) + (m2 + m3)) + ((m4 + m5) + (m6 + m7));
    }
    __syncthreads();

    int b = tid >> 6, ch = tid & 63;
    unsigned long long acc2[8];
    #pragma unroll
    for (int i = 0; i < 8; i++) acc2[i] = 0ull;
    const float4* wc = (const float4*)(g_Wcm + ch * 64);
    #pragma unroll 4
    for (int j4 = 0; j4 < 16; j4++) {
        float4 wv = __ldg(&wc[j4]);
        const float* x = s_S + (b * 64 + j4 * 4) * 20;
        FMA16P(acc2, wv.x, x);
        FMA16P(acc2, wv.y, x + 20);
        FMA16P(acc2, wv.z, x + 40);
        FMA16P(acc2, wv.w, x + 60);
    }
    float acc[16];
    UNPACK16(acc, acc2);

    float bc = __ldg(&g_bcm[ch]);
    float lsum = 0.f;
    #pragma unroll
    for (int cc = 0; cc < 16; cc++) {
        float q = __ldg(&g_Q[(size_t)(c0 + cc) * BD + tid]);
        float v = leaky(acc[cc] + q + (float)s_cnt[cc] * bc);
        acc[cc] = v;
        lsum += v;
        g_CnewT[(size_t)(c0 + cc) * BD + tid] = v;
    }
    float4* orow = (float4*)(outC + (size_t)tid * NC + c0);
    orow[0] = make_float4(acc[0], acc[1], acc[2], acc[3]);
    orow[1] = make_float4(acc[4], acc[5], acc[6], acc[7]);
    orow[2] = make_float4(acc[8], acc[9], acc[10], acc[11]);
    orow[3] = make_float4(acc[12], acc[13], acc[14], acc[15]);
    atomicAdd(&g_sumC[tid], lsum);
}

// Literal update: gather C_new + Wcl matvec + P.
__global__ __launch_bounds__(256) void k_literalUp(float* __restrict__ outL) {
    extern __shared__ float sm[];
    float* s_S   = sm;                     // 256*20
    int*   s_cnt = (int*)(s_S + 256 * 20); // 16
    int*   s_list = s_cnt + 16;            // 16*LCAP

    int tid = threadIdx.x;
    int l0 = blockIdx.x * 16;

    if (tid < 16) s_cnt[tid] = min(g_litCnt[l0 + tid], LCAP);
    __syncthreads();
    for (int idx = tid; idx < 16 * LCAP; idx += 256) {
        int cc = idx >> 6, i = idx & 63;
        if (i < s_cnt[cc]) s_list[idx] = g_litList[(size_t)(l0 + cc) * LCAP + i];
    }
    __syncthreads();

    #pragma unroll 1
    for (int cc = 0; cc < 16; cc++) {
        int cnt = s_cnt[cc];
        const int* lst = s_list + cc * LCAP;
        float m0 = 0.f, m1 = 0.f, m2 = 0.f, m3 = 0.f;
        float m4 = 0.f, m5 = 0.f, m6 = 0.f, m7 = 0.f;
        int i = 0;
        for (; i + 7 < cnt; i += 8) {
            m0 += __ldg(&g_CnewT[(size_t)lst[i]     * BD + tid]);
            m1 += __ldg(&g_CnewT[(size_t)lst[i + 1] * BD + tid]);
            m2 += __ldg(&g_CnewT[(size_t)lst[i + 2] * BD + tid]);
            m3 += __ldg(&g_CnewT[(size_t)lst[i + 3] * BD + tid]);
            m4 += __ldg(&g_CnewT[(size_t)lst[i + 4] * BD + tid]);
            m5 += __ldg(&g_CnewT[(size_t)lst[i + 5] * BD + tid]);
            m6 += __ldg(&g_CnewT[(size_t)lst[i + 6] * BD + tid]);
            m7 += __ldg(&g_CnewT[(size_t)lst[i + 7] * BD + tid]);
        }
        for (; i < cnt; i++) m0 += __ldg(&g_CnewT[(size_t)lst[i] * BD + tid]);
        s_S[tid * 20 + cc] = ((m0 + m1) + (m2 + m3)) + ((m4 + m5) + (m6 + m7));
    }
    __syncthreads();

    int b = tid >> 6, ch = tid & 63;
    unsigned long long acc2[8];
    #pragma unroll
    for (int i = 0; i < 8; i++) acc2[i] = 0ull;
    const float4* wl = (const float4*)(g_Wcl + ch * 64);
    #pragma unroll 4
    for (int j4 = 0; j4 < 16; j4++) {
        float4 wv = __ldg(&wl[j4]);
        const float* x = s_S + (b * 64 + j4 * 4) * 20;
        FMA16P(acc2, wv.x, x);
        FMA16P(acc2, wv.y, x + 20);
        FMA16P(acc2, wv.z, x + 40);
        FMA16P(acc2, wv.w, x + 60);
    }
    float acc[16];
    UNPACK16(acc, acc2);

    float bc = __ldg(&g_bcl[ch]);
    float lsum = 0.f;
    #pragma unroll
    for (int cc = 0; cc < 16; cc++) {
        float p = __ldg(&g_P[(size_t)(l0 + cc) * BD + tid]);
        float v = leaky(acc[cc] + p + (float)s_cnt[cc] * bc);
        acc[cc] = v;
        lsum += v;
    }
    float4* orow = (float4*)(outL + (size_t)tid * NL + l0);
    orow[0] = make_float4(acc[0], acc[1], acc[2], acc[3]);
    orow[1] = make_float4(acc[4], acc[5], acc[6], acc[7]);
    orow[2] = make_float4(acc[8], acc[9], acc[10], acc[11]);
    orow[3] = make_float4(acc[12], acc[13], acc[14], acc[15]);
    atomicAdd(&g_sumL[tid], lsum);
}

__global__ void k_U(const float* __restrict__ U, const float* __restrict__ WUu,
                    const float* __restrict__ bUu, float* __restrict__ out) {
    __shared__ float glb[4 * 192];
    int tid = threadIdx.x;
    int b = tid >> 6, ch = tid & 63;
    glb[b * 192 + ch]       = g_sumL[tid];
    glb[b * 192 + 64 + ch]  = g_sumC[tid];
    glb[b * 192 + 128 + ch] = U[tid];
    __syncthreads();
    float s = bUu[ch];
    #pragma unroll 8
    for (int i = 0; i < 192; i++) s += WUu[ch * 192 + i] * glb[b * 192 + i];
    out[tid] = leaky(s);
}

// ---------------- launch ----------------
extern "C" void kernel_launch(void* const* d_in, const int* in_sizes, int n_in,
                              void* d_out, int out_size) {
    const float* L     = (const float*)d_in[0];
    const float* C     = (const float*)d_in[1];
    const float* U     = (const float*)d_in[2];
    const float* A     = (const float*)d_in[3];
    const float* WLmsg = (const float*)d_in[5];
    const float* bLmsg = (const float*)d_in[6];
    const float* WCmsg = (const float*)d_in[7];
    const float* bCmsg = (const float*)d_in[8];
    const float* WLu   = (const float*)d_in[9];
    const float* bLu   = (const float*)d_in[10];
    const float* WCu   = (const float*)d_in[11];
    const float* bCu   = (const float*)d_in[12];
    const float* WUu   = (const float*)d_in[13];
    const float* bUu   = (const float*)d_in[14];
    float* out = (float*)d_out;

    const int smem_clause  = (256 * 20 + 16 + 16 * SCAPC) * 4;
    const int smem_literal = (256 * 20 + 16 + 16 * LCAP) * 4;
    cudaFuncSetAttribute(k_clauseUp,  cudaFuncAttributeMaxDynamicSharedMemorySize, smem_clause);
    cudaFuncSetAttribute(k_literalUp, cudaFuncAttributeMaxDynamicSharedMemorySize, smem_literal);

    k_zeroA<<<32, 256>>>();
    k_zeroB<<<64, 256>>>();
    k_zeroC<<<1, 256>>>();
    k_mega<<<MEGA_BLOCKS, 256>>>((const uint4*)A, L, C, WCu, WLmsg, bLmsg,
                                 WLu, WCmsg, bCmsg, bCu, bLu);
    k_clauseUp<<<NC / 16, 256, smem_clause>>>(out + OUT_C);
    k_literalUp<<<NL / 16, 256, smem_literal>>>(out + OUT_L);
    k_U<<<1, 256>>>(U, WUu, bUu, out + OUT_U);
}